// round 3
// baseline (speedup 1.0000x reference)
#include <cuda_runtime.h>

#define EPSF 1e-5f

static constexpr int WAYN = 32;
static constexpr int QN   = 4096;
static constexpr int DIMN = 640;
static constexpr int RRN  = 10;

// ---------------- scratch (device globals; no allocation) ----------------
__device__ float g_protos[WAYN * DIMN];
__device__ float g_pn[WAYN];
__device__ float g_part[16 * DIMN];
__device__ float g_c[WAYN];
__device__ float g_sp[WAYN];
__device__ float g_dis[WAYN * QN];
__device__ float g_T[WAYN];
__device__ float g_f10[WAYN];
__device__ float g_nid[WAYN * RRN];
__device__ int   g_nidx[WAYN * RRN];
__device__ float g_iw[WAYN * RRN];
__device__ float g_onw[WAYN];
__device__ float g_tmp[WAYN * DIMN];
__device__ float g_tn[WAYN];
__device__ float g_st[WAYN];

// ---------------- math helpers ----------------
__device__ __forceinline__ float expmap_scale(float nx, float c) {
    // scale s such that expmap0(x, c) = s * x, for ||x|| = nx
    float sc = sqrtf(c);
    float n  = fmaxf(nx, EPSF);
    float th = tanhf(sc * n);
    float s  = th / (sc * n);
    float ny = fmaxf(s * nx, EPSF);
    float maxn = 0.999f / sc;       // (1.0 - 0.001)/sc
    if (ny > maxn) s *= maxn / ny;
    return s;
}

__device__ __forceinline__ float pdist(float G, float c, float sp, float np_, float nq) {
    // Poincare distance given raw dot G = P.Q, norms np_, nq, scales sp (proto), c
    float sc = sqrtf(c);
    float sq = expmap_scale(nq, c);
    float xy = sp * sq * G;
    float uy = -xy;                       // u = -x
    float u2 = sp * sp * np_ * np_;
    float y2 = sq * sq * nq * nq;
    float A  = 1.f + 2.f * c * uy + c * y2;
    float B  = 1.f - c * u2;
    float num2 = A * A * u2 + 2.f * A * B * uy + B * B * y2;
    float den  = fmaxf(1.f + 2.f * c * uy + c * c * u2 * y2, EPSF);
    float nn   = sqrtf(fmaxf(num2, 0.f)) / den;
    float arg  = fminf(sc * nn, 1.f - EPSF);
    arg = fmaxf(arg, 0.f);
    return (2.f / sc) * atanhf(arg);
}

// ---------------- K1: protos + proto norms ----------------
__global__ void k_protos(const float* __restrict__ ds) {
    int w = blockIdx.x, t = threadIdx.x;
    __shared__ float red[256];
    float acc = 0.f;
    for (int d = t; d < DIMN; d += 256) {
        float s = 0.f;
#pragma unroll
        for (int sh = 0; sh < 5; sh++) s += ds[(sh * WAYN + w) * DIMN + d];
        float p = s * 0.2f;
        g_protos[w * DIMN + d] = p;
        acc += p * p;
    }
    red[t] = acc;
    __syncthreads();
    for (int o = 128; o; o >>= 1) { if (t < o) red[t] += red[t + o]; __syncthreads(); }
    if (t == 0) g_pn[w] = sqrtf(red[0]);
}

// ---------------- K2: deterministic column partial-sums for all_data ----------------
__global__ void k_colsum(const float* __restrict__ ds, const float* __restrict__ dq) {
    int c = blockIdx.x * 128 + threadIdx.x;     // 0..639
    int p = blockIdx.y;                          // 0..15
    int r0 = p * 266, r1 = min(r0 + 266, 4256);
    float acc = 0.f;
    for (int r = r0; r < r1; r++)
        acc += (r < 160) ? ds[r * DIMN + c] : dq[(r - 160) * DIMN + c];
    g_part[p * DIMN + c] = acc;
}

// ---------------- K3: controller MLP -> c[w], proto scale sp[w] ----------------
__global__ void k_ctrl(const float* __restrict__ W1, const float* __restrict__ b1,
                       const float* __restrict__ W2, const float* __restrict__ b2,
                       const float* __restrict__ W3, const float* __restrict__ b3) {
    int w = blockIdx.x, t = threadIdx.x;
    __shared__ float ci[2 * DIMN];
    __shared__ float h1[128];
    __shared__ float h2[64];
    for (int d = t; d < DIMN; d += 128) {
        ci[d] = g_protos[w * DIMN + d];
        float s = 0.f;
#pragma unroll
        for (int p = 0; p < 16; p++) s += g_part[p * DIMN + d];
        ci[DIMN + d] = s * (1.0f / 4256.0f);
    }
    __syncthreads();
    {
        float a = b1[t];
        for (int d = 0; d < 2 * DIMN; d++) a = fmaf(ci[d], W1[d * 128 + t], a);
        h1[t] = fmaxf(a, 0.f);
    }
    __syncthreads();
    if (t < 64) {
        float a = b2[t];
        for (int d = 0; d < 128; d++) a = fmaf(h1[d], W2[d * 64 + t], a);
        h2[t] = fmaxf(a, 0.f);
    }
    __syncthreads();
    if (t == 0) {
        float lg[5];
        for (int o = 0; o < 5; o++) {
            float a = b3[o];
            for (int d = 0; d < 64; d++) a = fmaf(h2[d], W3[d * 5 + o], a);
            lg[o] = a;
        }
        float m = lg[0];
        for (int o = 1; o < 5; o++) m = fmaxf(m, lg[o]);
        float se = 0.f, cv = 0.f;
        for (int o = 0; o < 5; o++) {
            float e = expf(lg[o] - m);
            se += e;
            cv += e * ((float)(o + 1) * 0.2f);   // cand = [1..5]*L/DIV
        }
        float c = cv / se;
        g_c[w]  = c;
        g_sp[w] = expmap_scale(g_pn[w], c);
    }
}

// ---------------- K4/K8: GEMM (32 x 32q tile) + distance epilogue ----------------
__global__ __launch_bounds__(256) void k_gemm_dist(const float* __restrict__ Bq,
                                                   float* __restrict__ outp, int pass) {
    const float* __restrict__ Amat = pass ? g_tmp : g_protos;
    const float* __restrict__ An   = pass ? g_tn  : g_pn;
    const float* __restrict__ Asc  = pass ? g_st  : g_sp;

    __shared__ float As[32][33];
    __shared__ float Bs[32][33];
    __shared__ float Rs[4][1024];
    __shared__ float qns[32];

    int t = threadIdx.x;
    int q0 = blockIdx.x * 32;
    int slice = t >> 6;       // 0..3  (k-slice)
    int ct = t & 63;
    int wt = ct & 7;          // 8 way-threads * 4 ways
    int qt = ct >> 3;         // 8 q-threads * 4 queries
    int lw = t >> 3;          // load row 0..31
    int lk = (t & 7) * 4;     // load k offset

    float acc[4][4];
#pragma unroll
    for (int i = 0; i < 4; i++)
#pragma unroll
        for (int j = 0; j < 4; j++) acc[i][j] = 0.f;

    float q2acc = 0.f;
    const float* arow = Amat + lw * DIMN + lk;
    const float* brow = Bq + (size_t)(q0 + lw) * DIMN + lk;

    for (int k0 = 0; k0 < DIMN; k0 += 32) {
        float4 av = *(const float4*)(arow + k0);
        float4 bv = *(const float4*)(brow + k0);
        As[lw][lk + 0] = av.x; As[lw][lk + 1] = av.y; As[lw][lk + 2] = av.z; As[lw][lk + 3] = av.w;
        Bs[lw][lk + 0] = bv.x; Bs[lw][lk + 1] = bv.y; Bs[lw][lk + 2] = bv.z; Bs[lw][lk + 3] = bv.w;
        q2acc += bv.x * bv.x + bv.y * bv.y + bv.z * bv.z + bv.w * bv.w;
        __syncthreads();
        int kb = slice * 8;
#pragma unroll
        for (int kk = 0; kk < 8; kk++) {
            int k = kb + kk;
            float a[4], b[4];
#pragma unroll
            for (int i = 0; i < 4; i++) a[i] = As[wt * 4 + i][k];
#pragma unroll
            for (int j = 0; j < 4; j++) b[j] = Bs[qt * 4 + j][k];
#pragma unroll
            for (int i = 0; i < 4; i++)
#pragma unroll
                for (int j = 0; j < 4; j++) acc[i][j] = fmaf(a[i], b[j], acc[i][j]);
        }
        __syncthreads();
    }

    // query norms: 8 loader-threads per row, reduce within groups of 8 lanes
    q2acc += __shfl_xor_sync(0xffffffffu, q2acc, 1);
    q2acc += __shfl_xor_sync(0xffffffffu, q2acc, 2);
    q2acc += __shfl_xor_sync(0xffffffffu, q2acc, 4);
    if ((t & 7) == 0) qns[lw] = sqrtf(q2acc);

#pragma unroll
    for (int i = 0; i < 4; i++)
#pragma unroll
        for (int j = 0; j < 4; j++)
            Rs[slice][(wt * 4 + i) * 32 + qt * 4 + j] = acc[i][j];
    __syncthreads();

#pragma unroll
    for (int r = 0; r < 4; r++) {
        int o = t + 256 * r;
        int w = o >> 5, q = o & 31;
        float G = Rs[0][o] + Rs[1][o] + Rs[2][o] + Rs[3][o];
        float d = pdist(G, g_c[w], Asc[w], An[w], qns[q]);
        if (pass == 0) g_dis[w * QN + q0 + q] = d;
        else           outp[(size_t)(q0 + q) * WAYN + w] = -d * (1.0f / 16.0f);
    }
}

// ---------------- K5: per-way top-10 (stable, ascending) + row sums ----------------
__global__ __launch_bounds__(512) void k_topk() {
    int w = blockIdx.x, t = threadIdx.x;
    __shared__ float sv[512 * RRN];
    __shared__ int   si[512 * RRN];
    __shared__ float red[512];

    float v[RRN]; int id[RRN];
#pragma unroll
    for (int i = 0; i < RRN; i++) { v[i] = __int_as_float(0x7f800000); id[i] = 0x7fffffff; }

    float sum = 0.f;
    const float* row = g_dis + w * QN;
    for (int i = 0; i < 8; i++) {
        int q = i * 512 + t;
        float x = row[q];
        sum += x;
        if (x < v[RRN - 1] || (x == v[RRN - 1] && q < id[RRN - 1])) {
            int p = RRN - 1;
            while (p > 0 && (x < v[p - 1] || (x == v[p - 1] && q < id[p - 1]))) {
                v[p] = v[p - 1]; id[p] = id[p - 1]; p--;
            }
            v[p] = x; id[p] = q;
        }
    }
    red[t] = sum;
#pragma unroll
    for (int i = 0; i < RRN; i++) { sv[t * RRN + i] = v[i]; si[t * RRN + i] = id[i]; }
    __syncthreads();

    for (int o = 256; o; o >>= 1) { if (t < o) red[t] += red[t + o]; __syncthreads(); }

    for (int off = 256; off >= 1; off >>= 1) {
        if (t < off) {
            float av[RRN], bv[RRN], mv[RRN];
            int   ai[RRN], bi[RRN], mi[RRN];
#pragma unroll
            for (int i = 0; i < RRN; i++) {
                av[i] = sv[t * RRN + i];          ai[i] = si[t * RRN + i];
                bv[i] = sv[(t + off) * RRN + i];  bi[i] = si[(t + off) * RRN + i];
            }
            int ia = 0, ib = 0;
#pragma unroll
            for (int i = 0; i < RRN; i++) {
                bool ta = (av[ia] < bv[ib]) || (av[ia] == bv[ib] && ai[ia] < bi[ib]);
                if (ta) { mv[i] = av[ia]; mi[i] = ai[ia]; ia++; }
                else    { mv[i] = bv[ib]; mi[i] = bi[ib]; ib++; }
            }
#pragma unroll
            for (int i = 0; i < RRN; i++) { sv[t * RRN + i] = mv[i]; si[t * RRN + i] = mi[i]; }
        }
        __syncthreads();
    }
    if (t < RRN) { g_nid[w * RRN + t] = sv[t]; g_nidx[w * RRN + t] = si[t]; }
    if (t == 0) {
        g_T[w] = red[0];
        float f = 0.f;
        for (int q = 0; q < RRN; q++) f += row[q];
        g_f10[w] = f;
    }
}

// ---------------- K6: stats + relation MLP -> i_w, onw ----------------
__global__ __launch_bounds__(1024) void k_small(const float* __restrict__ Wr1, const float* __restrict__ br1,
                                                const float* __restrict__ Wr2, const float* __restrict__ br2) {
    __shared__ float sT[32], sf10[32];
    __shared__ float snid[32][10];
    __shared__ int   sidx[32][10];
    __shared__ float scn[32][32];
    __shared__ float snod[32][10];
    int t = threadIdx.x;

    if (t < 32) { sT[t] = g_T[t]; sf10[t] = g_f10[t]; }
    if (t < 320) { int i = t / 10, k = t % 10; snid[i][k] = g_nid[t]; sidx[i][k] = g_nidx[t]; }
    __syncthreads();

    {   // colsum_near[i][j] = sum_k dis[j, idx_near[i,k]]
        int i = t >> 5, j = t & 31;
        float s = 0.f;
        for (int k = 0; k < 10; k++) s += g_dis[j * QN + sidx[i][k]];
        scn[i][j] = s;
    }
    if (t < 320) {  // n_o_d
        int i = t / 10, k = t % 10;
        int q = sidx[i][k];
        float s = 0.f;
        for (int j = 0; j < 32; j++) s += g_dis[j * QN + q];
        snod[i][k] = (s - snid[i][k]) * (1.0f / 31.0f);
    }
    __syncthreads();

    if (t < 32) {
        int i = t;
        float nsum = 0.f;
        for (int k = 0; k < 10; k++) nsum += snid[i][k];
        float oid = (sT[i] - nsum) * (1.0f / (float)(QN - RRN));
        float sa = 0.f;
        for (int j = 0; j < i; j++) sa += sT[j] - scn[i][j];
        float sb = 0.f;
        for (int j = i + 1; j < 32; j++) sb += sT[j] - sf10[j];
        float ood = (sa + sb) * (1.0f / (float)((WAYN - 1) * (QN - RRN)));

        float rin[22];
        for (int k = 0; k < 10; k++) { rin[k] = snid[i][k]; rin[10 + k] = snod[i][k]; }
        rin[20] = oid; rin[21] = ood;

        float hr[10];
        for (int r = 0; r < 10; r++) {
            float a = br1[r];
            for (int d = 0; d < 22; d++) a = fmaf(rin[d], Wr1[d * 10 + r], a);
            hr[r] = fmaxf(a, 0.f);
        }
        float orr[11];
        for (int j = 0; j < 11; j++) {
            float a = br2[j];
            for (int r = 0; r < 10; r++) a = fmaf(hr[r], Wr2[r * 11 + j], a);
            orr[j] = a;
        }
        float m = orr[0];
        for (int k = 1; k < 10; k++) m = fmaxf(m, orr[k]);
        float e[10], se = 0.f;
        for (int k = 0; k < 10; k++) { e[k] = expf(orr[k] - m); se += e[k]; }
        for (int k = 0; k < 10; k++) g_iw[i * 10 + k] = e[k] / se;
        g_onw[i] = 1.f / (1.f + expf(-orr[10]));
    }
}

// ---------------- K7: weighted query + test proto (raw) + its norm/scale ----------------
__global__ void k_wdq(const float* __restrict__ dq) {
    int w = blockIdx.x, t = threadIdx.x;   // 160 threads, float4 each
    __shared__ float iw[10];
    __shared__ int   id[10];
    __shared__ float red[256];
    if (t < 10) { iw[t] = g_iw[w * 10 + t]; id[t] = g_nidx[w * 10 + t]; }
    __syncthreads();
    float onw = g_onw[w];
    float om  = 1.f - onw;
    float4 wd = make_float4(0.f, 0.f, 0.f, 0.f);
#pragma unroll
    for (int k = 0; k < 10; k++) {
        float4 qv = *((const float4*)(dq + (size_t)id[k] * DIMN) + t);
        float wk = iw[k];
        wd.x = fmaf(wk, qv.x, wd.x); wd.y = fmaf(wk, qv.y, wd.y);
        wd.z = fmaf(wk, qv.z, wd.z); wd.w = fmaf(wk, qv.w, wd.w);
    }
    float4 pv = *((const float4*)(g_protos + w * DIMN) + t);
    float4 tm;
    tm.x = pv.x * onw + wd.x * om;
    tm.y = pv.y * onw + wd.y * om;
    tm.z = pv.z * onw + wd.z * om;
    tm.w = pv.w * onw + wd.w * om;
    *((float4*)(g_tmp + w * DIMN) + t) = tm;

    red[t] = tm.x * tm.x + tm.y * tm.y + tm.z * tm.z + tm.w * tm.w;
    if (t < 96) red[160 + t] = 0.f;
    __syncthreads();
    for (int o = 128; o; o >>= 1) { if (t < o) red[t] += red[t + o]; __syncthreads(); }
    if (t == 0) {
        float nt = sqrtf(red[0]);
        g_tn[w] = nt;
        g_st[w] = expmap_scale(nt, g_c[w]);
    }
}

// ---------------- launch ----------------
extern "C" void kernel_launch(void* const* d_in, const int* in_sizes, int n_in,
                              void* d_out, int out_size) {
    const float* ds  = (const float*)d_in[0];
    const float* dq  = (const float*)d_in[1];
    const float* W1  = (const float*)d_in[2];
    const float* b1  = (const float*)d_in[3];
    const float* W2  = (const float*)d_in[4];
    const float* b2  = (const float*)d_in[5];
    const float* W3  = (const float*)d_in[6];
    const float* b3  = (const float*)d_in[7];
    const float* Wr1 = (const float*)d_in[8];
    const float* br1 = (const float*)d_in[9];
    const float* Wr2 = (const float*)d_in[10];
    const float* br2 = (const float*)d_in[11];
    float* out = (float*)d_out;

    k_protos<<<32, 256>>>(ds);
    k_colsum<<<dim3(5, 16), 128>>>(ds, dq);
    k_ctrl<<<32, 128>>>(W1, b1, W2, b2, W3, b3);
    k_gemm_dist<<<128, 256>>>(dq, out, 0);
    k_topk<<<32, 512>>>();
    k_small<<<1, 1024>>>(Wr1, br1, Wr2, br2);
    k_wdq<<<32, 160>>>(dq);
    k_gemm_dist<<<128, 256>>>(dq, out, 1);
}